// round 1
// baseline (speedup 1.0000x reference)
#include <cuda_runtime.h>
#include <cuda_bf16.h>

#define POS_WEIGHT 1.0f
#define NEG_WEIGHT 8.0f
#define EPS 1e-7f

#define NBLK 1184      // 148 SMs * 8 blocks (full occupancy at 256 thr/blk)
#define NTH  256

__device__ float g_partials[NBLK];

__device__ __forceinline__ void bce_elem(float x, int t, float& sum) {
    // arg = (t==1) ? x+eps : (1-x)+eps ; w = (t==1) ? 1 : 8 ; sum += -w*log(arg)
    bool pos = (t == 1);
    float arg = pos ? (x + EPS) : ((1.0f - x) + EPS);
    float w   = pos ? POS_WEIGHT : NEG_WEIGHT;
    sum = fmaf(-w, __logf(arg), sum);
}

__device__ __forceinline__ void bce_vec4(const float4 xv, const int4 tv, float& sum) {
    bce_elem(xv.x, tv.x, sum);
    bce_elem(xv.y, tv.y, sum);
    bce_elem(xv.z, tv.z, sum);
    bce_elem(xv.w, tv.w, sum);
}

__global__ __launch_bounds__(NTH) void bce_partial_kernel(
    const float4* __restrict__ x4,
    const int4*  __restrict__ t4,
    int n4)
{
    const int tid    = blockIdx.x * NTH + threadIdx.x;
    const int stride = NBLK * NTH;

    float sum0 = 0.0f, sum1 = 0.0f;

    // Grid-stride, unrolled x2: issue 4 independent 128B loads per iteration
    // before any consumption, so each warp keeps >=4 wavefronts in flight.
    int i = tid;
    for (; i + stride < n4; i += 2 * stride) {
        float4 xa = x4[i];
        int4   ta = t4[i];
        float4 xb = x4[i + stride];
        int4   tb = t4[i + stride];
        bce_vec4(xa, ta, sum0);
        bce_vec4(xb, tb, sum1);
    }
    if (i < n4) {
        float4 xa = x4[i];
        int4   ta = t4[i];
        bce_vec4(xa, ta, sum0);
    }

    float sum = sum0 + sum1;

    // Warp reduce
    #pragma unroll
    for (int o = 16; o > 0; o >>= 1)
        sum += __shfl_xor_sync(0xffffffffu, sum, o);

    __shared__ float warp_sums[NTH / 32];
    if ((threadIdx.x & 31) == 0)
        warp_sums[threadIdx.x >> 5] = sum;
    __syncthreads();

    if (threadIdx.x == 0) {
        float v = 0.0f;
        #pragma unroll
        for (int w = 0; w < NTH / 32; w++)
            v += warp_sums[w];
        g_partials[blockIdx.x] = v;   // deterministic per-block partial
    }
}

__global__ __launch_bounds__(1024) void bce_final_kernel(float* __restrict__ out, float inv_n)
{
    __shared__ float s[1024];
    float v = 0.0f;
    for (int i = threadIdx.x; i < NBLK; i += 1024)
        v += g_partials[i];
    s[threadIdx.x] = v;
    __syncthreads();
    #pragma unroll
    for (int k = 512; k > 0; k >>= 1) {
        if (threadIdx.x < k) s[threadIdx.x] += s[threadIdx.x + k];
        __syncthreads();
    }
    if (threadIdx.x == 0)
        out[0] = s[0] * inv_n;
}

extern "C" void kernel_launch(void* const* d_in, const int* in_sizes, int n_in,
                              void* d_out, int out_size)
{
    const float* outputs = (const float*)d_in[0];
    const int*   targets = (const int*)d_in[1];
    float*       out     = (float*)d_out;

    const int n  = in_sizes[0];        // 33554432, divisible by 4
    const int n4 = n / 4;

    bce_partial_kernel<<<NBLK, NTH>>>(
        (const float4*)outputs, (const int4*)targets, n4);
    bce_final_kernel<<<1, 1024>>>(out, 1.0f / (float)n);
}

// round 2
// speedup vs baseline: 1.0622x; 1.0622x over previous
#include <cuda_runtime.h>
#include <cuda_bf16.h>

#define POS_WEIGHT 1.0f
#define NEG_WEIGHT 8.0f
#define EPS 1e-7f

#define NBLK 1184      // 148 SMs * 8 blocks (full occupancy at 256 thr/blk)
#define NTH  256

__device__ float        g_partials[NBLK];
__device__ unsigned int g_count = 0;   // self-resetting gate (graph-replay safe)

__device__ __forceinline__ void bce_elem(float x, int t, float& sum) {
    // arg = (t==1) ? x+eps : (1-x)+eps ; w = (t==1) ? 1 : 8 ; sum += -w*log(arg)
    bool pos = (t == 1);
    float arg = pos ? (x + EPS) : ((1.0f - x) + EPS);
    float w   = pos ? POS_WEIGHT : NEG_WEIGHT;
    sum = fmaf(-w, __logf(arg), sum);
}

__device__ __forceinline__ void bce_vec4(const float4 xv, const int4 tv, float& sum) {
    bce_elem(xv.x, tv.x, sum);
    bce_elem(xv.y, tv.y, sum);
    bce_elem(xv.z, tv.z, sum);
    bce_elem(xv.w, tv.w, sum);
}

__global__ __launch_bounds__(NTH) void bce_fused_kernel(
    const float4* __restrict__ x4,
    const int4*   __restrict__ t4,
    int n4,
    float* __restrict__ out,
    float inv_n)
{
    const int tid    = blockIdx.x * NTH + threadIdx.x;
    const int stride = NBLK * NTH;

    float sum0 = 0.0f, sum1 = 0.0f;

    // Grid-stride, unrolled x2: 4 independent 128B streaming loads in flight
    // per warp before any consumption. __ldcs = evict-first (single-touch data).
    int i = tid;
    for (; i + stride < n4; i += 2 * stride) {
        float4 xa = __ldcs(&x4[i]);
        int4   ta = __ldcs(&t4[i]);
        float4 xb = __ldcs(&x4[i + stride]);
        int4   tb = __ldcs(&t4[i + stride]);
        bce_vec4(xa, ta, sum0);
        bce_vec4(xb, tb, sum1);
    }
    if (i < n4) {
        float4 xa = __ldcs(&x4[i]);
        int4   ta = __ldcs(&t4[i]);
        bce_vec4(xa, ta, sum0);
    }

    float sum = sum0 + sum1;

    // Warp reduce
    #pragma unroll
    for (int o = 16; o > 0; o >>= 1)
        sum += __shfl_xor_sync(0xffffffffu, sum, o);

    __shared__ float warp_sums[NTH / 32];
    __shared__ bool  s_is_last;

    if ((threadIdx.x & 31) == 0)
        warp_sums[threadIdx.x >> 5] = sum;
    __syncthreads();

    if (threadIdx.x == 0) {
        float v = 0.0f;
        #pragma unroll
        for (int w = 0; w < NTH / 32; w++)
            v += warp_sums[w];
        g_partials[blockIdx.x] = v;        // deterministic per-block partial
        __threadfence();                   // make partial visible before gating
        unsigned int prev = atomicAdd(&g_count, 1u);
        s_is_last = (prev == NBLK - 1);
    }
    __syncthreads();

    // Last-arriving block performs the final reduction in FIXED index order
    // (no float atomics -> bitwise deterministic result every replay).
    if (s_is_last) {
        float v = 0.0f;
        for (int j = threadIdx.x; j < NBLK; j += NTH)
            v += g_partials[j];            // <=5 per thread, fixed order

        #pragma unroll
        for (int o = 16; o > 0; o >>= 1)
            v += __shfl_xor_sync(0xffffffffu, v, o);

        if ((threadIdx.x & 31) == 0)
            warp_sums[threadIdx.x >> 5] = v;
        __syncthreads();

        if (threadIdx.x == 0) {
            float tot = 0.0f;
            #pragma unroll
            for (int w = 0; w < NTH / 32; w++)
                tot += warp_sums[w];
            out[0]  = tot * inv_n;
            g_count = 0;                   // reset gate for next graph replay
        }
    }
}

extern "C" void kernel_launch(void* const* d_in, const int* in_sizes, int n_in,
                              void* d_out, int out_size)
{
    const float* outputs = (const float*)d_in[0];
    const int*   targets = (const int*)d_in[1];
    float*       out     = (float*)d_out;

    const int n  = in_sizes[0];        // 33554432, divisible by 4
    const int n4 = n / 4;

    bce_fused_kernel<<<NBLK, NTH>>>(
        (const float4*)outputs, (const int4*)targets, n4, out, 1.0f / (float)n);
}